// round 15
// baseline (speedup 1.0000x reference)
#include <cuda_runtime.h>
#include <cuda_bf16.h>
#include <cuda_fp16.h>
#include <cstdint>

#define BATCH 16
#define LQ    512
#define LC    2048
#define DIM   1024

// ---------------------------------------------------------------------------
// Device scratch (device-side only; symbols NEVER passed from host)
// ---------------------------------------------------------------------------
__device__ float         g_attn  [(size_t)BATCH * LC * LQ];    // fp32 logits
__device__ __nv_bfloat16 g_ctx_hi[(size_t)BATCH * LC * DIM];
__device__ __nv_bfloat16 g_ctx_lo[(size_t)BATCH * LC * DIM];
__device__ __nv_bfloat16 g_q_hi  [(size_t)BATCH * LQ * DIM];
__device__ __nv_bfloat16 g_q_lo  [(size_t)BATCH * LQ * DIM];
__device__ __half        g_q16   [(size_t)BATCH * LQ * DIM];   // fp16 q (GEMM2)
__device__ __half        g_w16   [(size_t)BATCH * LC * LQ];    // fp16 weights

// ---------------------------------------------------------------------------
// helpers
// ---------------------------------------------------------------------------
__device__ __forceinline__ void ldm4(uint32_t a, uint32_t& r0, uint32_t& r1,
                                     uint32_t& r2, uint32_t& r3) {
    asm volatile("ldmatrix.sync.aligned.m8n8.x4.shared.b16 {%0,%1,%2,%3}, [%4];"
                 : "=r"(r0), "=r"(r1), "=r"(r2), "=r"(r3) : "r"(a));
}
__device__ __forceinline__ void ldm4t(uint32_t a, uint32_t& r0, uint32_t& r1,
                                      uint32_t& r2, uint32_t& r3) {
    asm volatile("ldmatrix.sync.aligned.m8n8.x4.trans.shared.b16 {%0,%1,%2,%3}, [%4];"
                 : "=r"(r0), "=r"(r1), "=r"(r2), "=r"(r3) : "r"(a));
}
__device__ __forceinline__ void mma16816(float* c, uint32_t a0, uint32_t a1, uint32_t a2,
                                         uint32_t a3, uint32_t b0, uint32_t b1) {
    asm volatile(
        "mma.sync.aligned.m16n8k16.row.col.f32.bf16.bf16.f32 "
        "{%0,%1,%2,%3}, {%4,%5,%6,%7}, {%8,%9}, {%0,%1,%2,%3};"
        : "+f"(c[0]), "+f"(c[1]), "+f"(c[2]), "+f"(c[3])
        : "r"(a0), "r"(a1), "r"(a2), "r"(a3), "r"(b0), "r"(b1));
}
__device__ __forceinline__ void mma16816h(float* c, uint32_t a0, uint32_t a1, uint32_t a2,
                                          uint32_t a3, uint32_t b0, uint32_t b1) {
    asm volatile(
        "mma.sync.aligned.m16n8k16.row.col.f32.f16.f16.f32 "
        "{%0,%1,%2,%3}, {%4,%5,%6,%7}, {%8,%9}, {%0,%1,%2,%3};"
        : "+f"(c[0]), "+f"(c[1]), "+f"(c[2]), "+f"(c[3])
        : "r"(a0), "r"(a1), "r"(a2), "r"(a3), "r"(b0), "r"(b1));
}
__device__ __forceinline__ uint32_t smem_u32(const void* p) {
    uint32_t a;
    asm("{ .reg .u64 t; cvta.to.shared.u64 t, %1; cvt.u32.u64 %0, t; }" : "=r"(a) : "l"(p));
    return a;
}
__device__ __forceinline__ void cp16(uint32_t dst, const void* src) {
    asm volatile("cp.async.cg.shared.global [%0], [%1], 16;" :: "r"(dst), "l"(src));
}
__device__ __forceinline__ void cp_commit() { asm volatile("cp.async.commit_group;"); }
template <int N>
__device__ __forceinline__ void cp_wait() { asm volatile("cp.async.wait_group %0;" :: "n"(N)); }

// split float4 into packed bf16 hi pair-words and lo pair-words
__device__ __forceinline__ void split4(float4 v, uint32_t& h01, uint32_t& h23,
                                       uint32_t& l01, uint32_t& l23) {
    __nv_bfloat16 hx = __float2bfloat16(v.x), hy = __float2bfloat16(v.y);
    __nv_bfloat16 hz = __float2bfloat16(v.z), hw = __float2bfloat16(v.w);
    float lx = v.x - __bfloat162float(hx), ly = v.y - __bfloat162float(hy);
    float lz = v.z - __bfloat162float(hz), lw = v.w - __bfloat162float(hw);
    __nv_bfloat162 H0(hx, hy), H1(hz, hw);
    __nv_bfloat162 L0 = __floats2bfloat162_rn(lx, ly), L1 = __floats2bfloat162_rn(lz, lw);
    h01 = *(uint32_t*)&H0; h23 = *(uint32_t*)&H1;
    l01 = *(uint32_t*)&L0; l23 = *(uint32_t*)&L1;
}
__device__ __forceinline__ uint2 pack4h(float4 v) {
    __half2 a(__float2half_rn(v.x), __float2half_rn(v.y));
    __half2 b(__float2half_rn(v.z), __float2half_rn(v.w));
    return make_uint2(*(uint32_t*)&a, *(uint32_t*)&b);
}

// ---------------------------------------------------------------------------
// Operand prep kernels
// ---------------------------------------------------------------------------
__global__ __launch_bounds__(256)
void ba_split_ctx(const float* __restrict__ src)
{
    const size_t i = (size_t)blockIdx.x * 256 + threadIdx.x;   // float4 index
    float4 v = ((const float4*)src)[i];
    uint32_t h01, h23, l01, l23;
    split4(v, h01, h23, l01, l23);
    ((uint2*)g_ctx_hi)[i] = make_uint2(h01, h23);
    ((uint2*)g_ctx_lo)[i] = make_uint2(l01, l23);
}
__global__ __launch_bounds__(256)
void ba_split_q(const float* __restrict__ src)
{
    const size_t i = (size_t)blockIdx.x * 256 + threadIdx.x;
    float4 v = ((const float4*)src)[i];
    uint32_t h01, h23, l01, l23;
    split4(v, h01, h23, l01, l23);
    ((uint2*)g_q_hi)[i] = make_uint2(h01, h23);
    ((uint2*)g_q_lo)[i] = make_uint2(l01, l23);
    ((uint2*)g_q16)[i]  = pack4h(v);
}

// ---------------------------------------------------------------------------
// GEMM1: logits = ctx @ q^T (3-MMA bf16 split, operands pre-split) -> g_attn
// CTA 128x128, 256 thr, warp 64x32, BK=16, 4-stage cp.async (wait<2> ->
// 3 K-tiles of load slack, covers DRAM latency).
// ---------------------------------------------------------------------------
#define ROW1  48                   // 16 bf16 = 32B + 16B pad (conflict-free)
#define STG1  (4 * 128 * ROW1)     // 24576 per stage
#define NST   4

__global__ __launch_bounds__(256, 2)
void ba_gemm1(void)
{
    constexpr int NT = DIM / 16;   // 64
    constexpr int AH = 0, AL = 128 * ROW1, BH = 2 * 128 * ROW1, BL = 3 * 128 * ROW1;

    extern __shared__ __align__(16) char sm[];
    const uint32_t sb = smem_u32(sm);

    const int tid  = threadIdx.x;
    const int lane = tid & 31;
    const int warp = tid >> 5;
    const int wm   = warp & 1;
    const int wn   = warp >> 1;        // 0..3, n offset 32*wn
    const int b  = blockIdx.z;
    const int yT = blockIdx.y;
    const int xT = blockIdx.x;

    const char* Ahg = (const char*)g_ctx_hi + ((size_t)b * LC + (size_t)yT * 128) * DIM * 2;
    const char* Alg = (const char*)g_ctx_lo + ((size_t)b * LC + (size_t)yT * 128) * DIM * 2;
    const char* Bhg = (const char*)g_q_hi  + ((size_t)b * LQ + (size_t)xT * 128) * DIM * 2;
    const char* Blg = (const char*)g_q_lo  + ((size_t)b * LQ + (size_t)xT * 128) * DIM * 2;

    const int r = tid >> 1, c = (tid & 1) * 16;   // 128 rows x 32B per tile

    auto cps = [&](int slot, int kt) {
        const uint32_t s0 = sb + slot * STG1;
        const size_t g = (size_t)r * (DIM * 2) + (size_t)kt * 32 + c;
        const uint32_t so = r * ROW1 + c;
        cp16(s0 + AH + so, Ahg + g);
        cp16(s0 + AL + so, Alg + g);
        cp16(s0 + BH + so, Bhg + g);
        cp16(s0 + BL + so, Blg + g);
        cp_commit();
    };

    float acc[4][4][4];
#pragma unroll
    for (int m = 0; m < 4; m++)
#pragma unroll
        for (int n = 0; n < 4; n++)
#pragma unroll
            for (int j = 0; j < 4; j++) acc[m][n][j] = 0.f;

    cps(0, 0); cps(1, 1); cps(2, 2);

    const int lrow = lane & 15;
    const int lkb  = lane & 16;

    for (int kt = 0; kt < NT; kt++) {
        cp_wait<2>();                  // stage kt resident (kt+1, kt+2 may fly)
        __syncthreads();               // all warps done with slot (kt-1)&3
        if (kt + 3 < NT) cps((kt + 3) & 3, kt + 3);
        else             cp_commit();  // keep group-count invariant

        const uint32_t s0 = (kt & 3) * STG1;

        uint32_t ahf[4][4], alf[4][4];
#pragma unroll
        for (int mt = 0; mt < 4; mt++) {
            uint32_t ra = sb + s0 + AH + (wm * 64 + mt * 16 + lrow) * ROW1 + lkb;
            ldm4(ra, ahf[mt][0], ahf[mt][1], ahf[mt][2], ahf[mt][3]);
            uint32_t rl = sb + s0 + AL + (wm * 64 + mt * 16 + lrow) * ROW1 + lkb;
            ldm4(rl, alf[mt][0], alf[mt][1], alf[mt][2], alf[mt][3]);
        }
#pragma unroll
        for (int p = 0; p < 2; p++) {
            uint32_t bh[4], bl[4];
            uint32_t rb = sb + s0 + BH + (wn * 32 + p * 16 + lrow) * ROW1 + lkb;
            ldm4(rb, bh[0], bh[1], bh[2], bh[3]);
            uint32_t rc = sb + s0 + BL + (wn * 32 + p * 16 + lrow) * ROW1 + lkb;
            ldm4(rc, bl[0], bl[1], bl[2], bl[3]);
#pragma unroll
            for (int mt = 0; mt < 4; mt++) {
                mma16816(acc[mt][2 * p],     ahf[mt][0], ahf[mt][1], ahf[mt][2], ahf[mt][3], bh[0], bh[2]);
                mma16816(acc[mt][2 * p + 1], ahf[mt][0], ahf[mt][1], ahf[mt][2], ahf[mt][3], bh[1], bh[3]);
                mma16816(acc[mt][2 * p],     alf[mt][0], alf[mt][1], alf[mt][2], alf[mt][3], bh[0], bh[2]);
                mma16816(acc[mt][2 * p + 1], alf[mt][0], alf[mt][1], alf[mt][2], alf[mt][3], bh[1], bh[3]);
                mma16816(acc[mt][2 * p],     ahf[mt][0], ahf[mt][1], ahf[mt][2], ahf[mt][3], bl[0], bl[2]);
                mma16816(acc[mt][2 * p + 1], ahf[mt][0], ahf[mt][1], ahf[mt][2], ahf[mt][3], bl[1], bl[3]);
            }
        }
    }

    float* Cg = (float*)g_attn;
    const size_t rbase = (size_t)b * LC + (size_t)yT * 128 + wm * 64 + (lane >> 2);
    const int    cbase = xT * 128 + wn * 32 + (lane & 3) * 2;
#pragma unroll
    for (int mt = 0; mt < 4; mt++) {
#pragma unroll
        for (int nt = 0; nt < 4; nt++) {
            size_t r0 = (rbase + mt * 16) * LQ + cbase + nt * 8;
            *(float2*)(Cg + r0)             = make_float2(acc[mt][nt][0], acc[mt][nt][1]);
            *(float2*)(Cg + r0 + 8ull * LQ) = make_float2(acc[mt][nt][2], acc[mt][nt][3]);
        }
    }
}

// ---------------------------------------------------------------------------
// GEMM2 (fp16 single-MMA): attn[c][d] = w16[c][q] . q16[q][d] -> out right half
//        + fused ctx 128x128 tile copy into out LEFT half.
// CTA 128x128, 256 thr, warp 64x32, BK=32, 4-stage cp.async.
// ---------------------------------------------------------------------------
#define ROW2A 80                   // 32 fp16 = 64B + 16B pad (conflict-free)
#define ROW2B 272                  // 128 fp16 = 256B + 16B pad
#define STG2  (128 * ROW2A + 32 * ROW2B)   // 10240 + 8704 = 18944

__global__ __launch_bounds__(256, 2)
void ba_gemm2(const float* __restrict__ actx, float* __restrict__ gout)
{
    constexpr int NT = LQ / 32;    // 16
    constexpr int AOFF = 0, BOFF = 128 * ROW2A;

    extern __shared__ __align__(16) char sm[];
    const uint32_t sb = smem_u32(sm);

    const int tid  = threadIdx.x;
    const int lane = tid & 31;
    const int warp = tid >> 5;
    const int wm   = warp & 1;
    const int wn   = warp >> 1;        // 0..3, n offset 32*wn
    const int b  = blockIdx.z;
    const int yT = blockIdx.y;
    const int xT = blockIdx.x;

    const char* Aw = (const char*)g_w16 + ((size_t)b * LC + (size_t)yT * 128) * LQ * 2;
    const char* Bq = (const char*)g_q16 + ((size_t)b * LQ * DIM + (size_t)xT * 128) * 2;

    const int r2 = tid >> 1, c2 = (tid & 1) * 32;   // A: 128 rows x 64B
    const int rb = tid >> 3, cb = (tid & 7) * 32;   // B: 32 k-rows x 256B

    auto cps = [&](int slot, int kt) {
        const uint32_t s0 = sb + slot * STG2;
        const size_t ga = (size_t)r2 * (LQ * 2) + (size_t)kt * 64 + c2;
        cp16(s0 + AOFF + r2 * ROW2A + c2,      Aw + ga);
        cp16(s0 + AOFF + r2 * ROW2A + c2 + 16, Aw + ga + 16);
        const size_t gb = (size_t)(kt * 32 + rb) * (DIM * 2) + cb;
        cp16(s0 + BOFF + rb * ROW2B + cb,      Bq + gb);
        cp16(s0 + BOFF + rb * ROW2B + cb + 16, Bq + gb + 16);
        cp_commit();
    };

    float acc[4][4][4];
#pragma unroll
    for (int m = 0; m < 4; m++)
#pragma unroll
        for (int n = 0; n < 4; n++)
#pragma unroll
            for (int j = 0; j < 4; j++) acc[m][n][j] = 0.f;

    cps(0, 0); cps(1, 1); cps(2, 2);

    const int lrow = lane & 15;
    const int lkb  = lane & 16;

    for (int kt = 0; kt < NT; kt++) {
        cp_wait<2>();
        __syncthreads();
        if (kt + 3 < NT) cps((kt + 3) & 3, kt + 3);
        else             cp_commit();

        const uint32_t s0 = (kt & 3) * STG2;
#pragma unroll
        for (int ks = 0; ks < 2; ks++) {          // two k16 steps (BK=32)
            const int lk = ks * 32 + lkb;
            uint32_t af[4][4];
#pragma unroll
            for (int mt = 0; mt < 4; mt++) {
                uint32_t ra = sb + s0 + AOFF + (wm * 64 + mt * 16 + lrow) * ROW2A + lk;
                ldm4(ra, af[mt][0], af[mt][1], af[mt][2], af[mt][3]);
            }
#pragma unroll
            for (int p = 0; p < 2; p++) {
                uint32_t bh[4];
                uint32_t rbA = sb + s0 + BOFF + (ks * 16 + lrow) * ROW2B
                             + (wn * 32 + p * 16) * 2 + lkb;
                ldm4t(rbA, bh[0], bh[1], bh[2], bh[3]);
#pragma unroll
                for (int mt = 0; mt < 4; mt++) {
                    mma16816h(acc[mt][2 * p],     af[mt][0], af[mt][1], af[mt][2], af[mt][3], bh[0], bh[1]);
                    mma16816h(acc[mt][2 * p + 1], af[mt][0], af[mt][1], af[mt][2], af[mt][3], bh[2], bh[3]);
                }
            }
        }
    }

    // epilogue -> out right half
    const size_t rbase = (size_t)b * LC + (size_t)yT * 128 + wm * 64 + (lane >> 2);
    const int    cbase = DIM + xT * 128 + wn * 32 + (lane & 3) * 2;
#pragma unroll
    for (int mt = 0; mt < 4; mt++) {
#pragma unroll
        for (int nt = 0; nt < 4; nt++) {
            size_t r0 = (rbase + mt * 16) * (2 * DIM) + cbase + nt * 8;
            *(float2*)(gout + r0)                    = make_float2(acc[mt][nt][0], acc[mt][nt][1]);
            *(float2*)(gout + r0 + 8ull * (2 * DIM)) = make_float2(acc[mt][nt][2], acc[mt][nt][3]);
        }
    }

    // fused ctx copy into out LEFT half: this CTA's 128x128 tile
    {
        const float4* csrc = (const float4*)(actx + ((size_t)b * LC + (size_t)yT * 128) * DIM
                                             + (size_t)xT * 128);
        float4* cdst = (float4*)(gout + ((size_t)b * LC + (size_t)yT * 128) * (2 * DIM)
                                 + (size_t)xT * 128);
        const int crow = tid >> 5;      // 0..7
        const int ccol = tid & 31;      // 32 float4 = 128 floats
#pragma unroll
        for (int it = 0; it < 16; it++) {
            cdst[(size_t)(crow + it * 8) * (2 * DIM / 4) + ccol] =
                csrc[(size_t)(crow + it * 8) * (DIM / 4) + ccol];
        }
    }
}

// ---------------------------------------------------------------------------
// Warp-per-row softmax over 512 logits: fp32 in (g_attn), fp16 out (g_w16).
// ---------------------------------------------------------------------------
__global__ __launch_bounds__(256)
void ba_softmax(void)
{
    const int wid = threadIdx.x >> 5, lane = threadIdx.x & 31;
    const size_t row = (size_t)blockIdx.x * 8 + wid;
    const float4* p = (const float4*)(g_attn + row * LQ);

    float4 v[4];
    float mx = -1e30f;
#pragma unroll
    for (int i = 0; i < 4; i++) {
        v[i] = p[i * 32 + lane];
        mx = fmaxf(mx, fmaxf(fmaxf(v[i].x, v[i].y), fmaxf(v[i].z, v[i].w)));
    }
#pragma unroll
    for (int o = 16; o > 0; o >>= 1) mx = fmaxf(mx, __shfl_xor_sync(0xFFFFFFFFu, mx, o));

    float sum = 0.f;
#pragma unroll
    for (int i = 0; i < 4; i++) {
        v[i].x = __expf(v[i].x - mx); v[i].y = __expf(v[i].y - mx);
        v[i].z = __expf(v[i].z - mx); v[i].w = __expf(v[i].w - mx);
        sum += (v[i].x + v[i].y) + (v[i].z + v[i].w);
    }
#pragma unroll
    for (int o = 16; o > 0; o >>= 1) sum += __shfl_xor_sync(0xFFFFFFFFu, sum, o);

    const float inv = 1.0f / sum;
    uint2* pw = (uint2*)(g_w16 + row * LQ);
#pragma unroll
    for (int i = 0; i < 4; i++) {
        v[i].x *= inv; v[i].y *= inv; v[i].z *= inv; v[i].w *= inv;
        pw[i * 32 + lane] = pack4h(v[i]);
    }
}

// ---------------------------------------------------------------------------
extern "C" void kernel_launch(void* const* d_in, const int* in_sizes, int n_in,
                              void* d_out, int out_size)
{
    const float* question = (const float*)d_in[0];
    const float* context  = (const float*)d_in[1];
    if (in_sizes[0] > in_sizes[1]) {
        const float* t = question; question = context; context = t;
    }
    float* out = (float*)d_out;

    cudaFuncSetAttribute(ba_gemm1, cudaFuncAttributeMaxDynamicSharedMemorySize, NST * STG1);
    cudaFuncSetAttribute(ba_gemm2, cudaFuncAttributeMaxDynamicSharedMemorySize, NST * STG2);

    // operand prep
    ba_split_ctx<<<(size_t)BATCH * LC * DIM / 4 / 256, 256>>>(context);
    ba_split_q  <<<(size_t)BATCH * LQ * DIM / 4 / 256, 256>>>(question);

    // logits = ctx @ q^T -> g_attn (3-MMA bf16 split, deep cp.async pipeline)
    ba_gemm1<<<dim3(LQ / 128, LC / 128, BATCH), 256, NST * STG1>>>();
    // softmax -> fp16 weights
    ba_softmax<<<BATCH * LC / 8, 256>>>();
    // attn_out = w16 @ q16 (single fp16 MMA, BK=32) -> right half + fused copy
    ba_gemm2<<<dim3(DIM / 128, LC / 128, BATCH), 256, NST * STG2>>>(context, out);
}

// round 16
// speedup vs baseline: 1.1548x; 1.1548x over previous
#include <cuda_runtime.h>
#include <cuda_bf16.h>
#include <cuda_fp16.h>
#include <cstdint>

#define BATCH 16
#define LQ    512
#define LC    2048
#define DIM   1024

// ---------------------------------------------------------------------------
// Device scratch (device-side only; symbols NEVER passed from host)
// ---------------------------------------------------------------------------
__device__ float         g_attn[(size_t)BATCH * LC * LQ];     // fp32 logits
__device__ __nv_bfloat16 g_q_hi[(size_t)BATCH * LQ * DIM];
__device__ __nv_bfloat16 g_q_lo[(size_t)BATCH * LQ * DIM];
__device__ __half        g_q16 [(size_t)BATCH * LQ * DIM];    // fp16 q  (GEMM2)
__device__ __half        g_w16 [(size_t)BATCH * LC * LQ];     // fp16 softmax weights

// ---------------------------------------------------------------------------
// helpers
// ---------------------------------------------------------------------------
__device__ __forceinline__ void ldm4(uint32_t a, uint32_t& r0, uint32_t& r1,
                                     uint32_t& r2, uint32_t& r3) {
    asm volatile("ldmatrix.sync.aligned.m8n8.x4.shared.b16 {%0,%1,%2,%3}, [%4];"
                 : "=r"(r0), "=r"(r1), "=r"(r2), "=r"(r3) : "r"(a));
}
__device__ __forceinline__ void ldm4t(uint32_t a, uint32_t& r0, uint32_t& r1,
                                      uint32_t& r2, uint32_t& r3) {
    asm volatile("ldmatrix.sync.aligned.m8n8.x4.trans.shared.b16 {%0,%1,%2,%3}, [%4];"
                 : "=r"(r0), "=r"(r1), "=r"(r2), "=r"(r3) : "r"(a));
}
__device__ __forceinline__ void mma16816(float* c, uint32_t a0, uint32_t a1, uint32_t a2,
                                         uint32_t a3, uint32_t b0, uint32_t b1) {
    asm volatile(
        "mma.sync.aligned.m16n8k16.row.col.f32.bf16.bf16.f32 "
        "{%0,%1,%2,%3}, {%4,%5,%6,%7}, {%8,%9}, {%0,%1,%2,%3};"
        : "+f"(c[0]), "+f"(c[1]), "+f"(c[2]), "+f"(c[3])
        : "r"(a0), "r"(a1), "r"(a2), "r"(a3), "r"(b0), "r"(b1));
}
__device__ __forceinline__ void mma16816h(float* c, uint32_t a0, uint32_t a1, uint32_t a2,
                                          uint32_t a3, uint32_t b0, uint32_t b1) {
    asm volatile(
        "mma.sync.aligned.m16n8k16.row.col.f32.f16.f16.f32 "
        "{%0,%1,%2,%3}, {%4,%5,%6,%7}, {%8,%9}, {%0,%1,%2,%3};"
        : "+f"(c[0]), "+f"(c[1]), "+f"(c[2]), "+f"(c[3])
        : "r"(a0), "r"(a1), "r"(a2), "r"(a3), "r"(b0), "r"(b1));
}
__device__ __forceinline__ uint32_t smem_u32(const void* p) {
    uint32_t a;
    asm("{ .reg .u64 t; cvta.to.shared.u64 t, %1; cvt.u32.u64 %0, t; }" : "=r"(a) : "l"(p));
    return a;
}
// split float4 into packed bf16 hi pair-words and lo pair-words
__device__ __forceinline__ void split4(float4 v, uint32_t& h01, uint32_t& h23,
                                       uint32_t& l01, uint32_t& l23) {
    __nv_bfloat16 hx = __float2bfloat16(v.x), hy = __float2bfloat16(v.y);
    __nv_bfloat16 hz = __float2bfloat16(v.z), hw = __float2bfloat16(v.w);
    float lx = v.x - __bfloat162float(hx), ly = v.y - __bfloat162float(hy);
    float lz = v.z - __bfloat162float(hz), lw = v.w - __bfloat162float(hw);
    __nv_bfloat162 H0(hx, hy), H1(hz, hw);
    __nv_bfloat162 L0 = __floats2bfloat162_rn(lx, ly), L1 = __floats2bfloat162_rn(lz, lw);
    h01 = *(uint32_t*)&H0; h23 = *(uint32_t*)&H1;
    l01 = *(uint32_t*)&L0; l23 = *(uint32_t*)&L1;
}
// pack float4 -> two half2 words
__device__ __forceinline__ uint2 pack4h(float4 v) {
    __half2 a(__float2half_rn(v.x), __float2half_rn(v.y));
    __half2 b(__float2half_rn(v.z), __float2half_rn(v.w));
    return make_uint2(*(uint32_t*)&a, *(uint32_t*)&b);
}

// ---------------------------------------------------------------------------
// Q pre-split: fp32 -> bf16 hi/lo (GEMM1) + fp16 (GEMM2)
// ---------------------------------------------------------------------------
__global__ __launch_bounds__(256)
void ba_split_q(const float* __restrict__ src)
{
    const size_t i = (size_t)blockIdx.x * 256 + threadIdx.x;   // float4 index
    float4 v = ((const float4*)src)[i];
    uint32_t h01, h23, l01, l23;
    split4(v, h01, h23, l01, l23);
    ((uint2*)g_q_hi)[i] = make_uint2(h01, h23);
    ((uint2*)g_q_lo)[i] = make_uint2(l01, l23);
    ((uint2*)g_q16)[i]  = pack4h(v);
}

// ---------------------------------------------------------------------------
// GEMM1 (R14 verbatim): logits = ctx @ q^T -> g_attn
// Split-bf16 (3 MMAs), CTA 128x128, 256 thr, warp 64x32, BK=16, double-buffered.
// ---------------------------------------------------------------------------
#define AROWB 48                   // 16 bf16 = 32B + 16B pad (conflict-free)

__global__ __launch_bounds__(256, 2)
void ba_gemm1(const float* __restrict__ actx)
{
    constexpr int KT = DIM;
    constexpr int NT = KT / 16;
    constexpr int STAGE = 4 * 128 * AROWB;                         // 24576
    constexpr int AH = 0, AL = 128 * AROWB, BH = 2 * 128 * AROWB, BL = 3 * 128 * AROWB;

    __shared__ __align__(16) char sm[2 * STAGE];
    const uint32_t sb = smem_u32(sm);

    const int tid  = threadIdx.x;
    const int lane = tid & 31;
    const int warp = tid >> 5;
    const int wm   = warp & 1;
    const int wn   = warp >> 1;        // 0..3, n offset 32*wn
    const int b  = blockIdx.z;
    const int yT = blockIdx.y;
    const int xT = blockIdx.x;

    const float* Abase_f = actx + ((size_t)b * LC + (size_t)yT * 128) * DIM;
    const char* Bqh = (const char*)g_q_hi + ((size_t)b * LQ + (size_t)xT * 128) * DIM * 2;
    const char* Bql = (const char*)g_q_lo + ((size_t)b * LQ + (size_t)xT * 128) * DIM * 2;

    const int ar = tid >> 2, ac = tid & 3;          // A fp32: rows ar, ar+64
    const int br = tid >> 1, bc = (tid & 1) * 16;   // B bf16: row br, 16B chunk

    float4 pa0, pa1;
    uint4  pbh, pbl;

    auto ldg_tiles = [&](int kt) {
        pa0 = *(const float4*)(Abase_f + (size_t)ar * DIM + kt * 16 + ac * 4);
        pa1 = *(const float4*)(Abase_f + (size_t)(ar + 64) * DIM + kt * 16 + ac * 4);
        pbh = *(const uint4*)(Bqh + (size_t)br * (DIM * 2) + kt * 32 + bc);
        pbl = *(const uint4*)(Bql + (size_t)br * (DIM * 2) + kt * 32 + bc);
    };
    auto sts_stage = [&](uint32_t s0) {
        uint32_t h0, h1, l0, l1;
        split4(pa0, h0, h1, l0, l1);
        *(uint2*)(sm + (s0 + AH + ar * AROWB + ac * 8))        = make_uint2(h0, h1);
        *(uint2*)(sm + (s0 + AL + ar * AROWB + ac * 8))        = make_uint2(l0, l1);
        split4(pa1, h0, h1, l0, l1);
        *(uint2*)(sm + (s0 + AH + (ar + 64) * AROWB + ac * 8)) = make_uint2(h0, h1);
        *(uint2*)(sm + (s0 + AL + (ar + 64) * AROWB + ac * 8)) = make_uint2(l0, l1);
        *(uint4*)(sm + (s0 + BH + br * AROWB + bc)) = pbh;
        *(uint4*)(sm + (s0 + BL + br * AROWB + bc)) = pbl;
    };

    float acc[4][4][4];
#pragma unroll
    for (int m = 0; m < 4; m++)
#pragma unroll
        for (int n = 0; n < 4; n++)
#pragma unroll
            for (int j = 0; j < 4; j++) acc[m][n][j] = 0.f;

    ldg_tiles(0);
    sts_stage(0);
    __syncthreads();

    const int lrow = lane & 15;
    const int lkb  = lane & 16;

    for (int kt = 0; kt < NT; kt++) {
        const uint32_t s0 = (kt & 1) * STAGE;
        if (kt + 1 < NT) ldg_tiles(kt + 1);

        uint32_t ahf[4][4], alf[4][4];
#pragma unroll
        for (int mt = 0; mt < 4; mt++) {
            uint32_t ra = sb + s0 + AH + (wm * 64 + mt * 16 + lrow) * AROWB + lkb;
            ldm4(ra, ahf[mt][0], ahf[mt][1], ahf[mt][2], ahf[mt][3]);
            uint32_t rl = sb + s0 + AL + (wm * 64 + mt * 16 + lrow) * AROWB + lkb;
            ldm4(rl, alf[mt][0], alf[mt][1], alf[mt][2], alf[mt][3]);
        }
#pragma unroll
        for (int p = 0; p < 2; p++) {
            uint32_t bh[4], bl[4];
            uint32_t rb = sb + s0 + BH + (wn * 32 + p * 16 + lrow) * AROWB + lkb;
            ldm4(rb, bh[0], bh[1], bh[2], bh[3]);
            uint32_t rc = sb + s0 + BL + (wn * 32 + p * 16 + lrow) * AROWB + lkb;
            ldm4(rc, bl[0], bl[1], bl[2], bl[3]);
#pragma unroll
            for (int mt = 0; mt < 4; mt++) {
                mma16816(acc[mt][2 * p],     ahf[mt][0], ahf[mt][1], ahf[mt][2], ahf[mt][3], bh[0], bh[2]);
                mma16816(acc[mt][2 * p + 1], ahf[mt][0], ahf[mt][1], ahf[mt][2], ahf[mt][3], bh[1], bh[3]);
                mma16816(acc[mt][2 * p],     alf[mt][0], alf[mt][1], alf[mt][2], alf[mt][3], bh[0], bh[2]);
                mma16816(acc[mt][2 * p + 1], alf[mt][0], alf[mt][1], alf[mt][2], alf[mt][3], bh[1], bh[3]);
                mma16816(acc[mt][2 * p],     ahf[mt][0], ahf[mt][1], ahf[mt][2], ahf[mt][3], bl[0], bl[2]);
                mma16816(acc[mt][2 * p + 1], ahf[mt][0], ahf[mt][1], ahf[mt][2], ahf[mt][3], bl[1], bl[3]);
            }
        }

        if (kt + 1 < NT) sts_stage(((kt + 1) & 1) * STAGE);
        __syncthreads();
    }

    float* Cg = (float*)g_attn;
    const size_t rbase = (size_t)b * LC + (size_t)yT * 128 + wm * 64 + (lane >> 2);
    const int    cbase = xT * 128 + wn * 32 + (lane & 3) * 2;
#pragma unroll
    for (int mt = 0; mt < 4; mt++) {
#pragma unroll
        for (int nt = 0; nt < 4; nt++) {
            size_t r0 = (rbase + mt * 16) * LQ + cbase + nt * 8;
            *(float2*)(Cg + r0)             = make_float2(acc[mt][nt][0], acc[mt][nt][1]);
            *(float2*)(Cg + r0 + 8ull * LQ) = make_float2(acc[mt][nt][2], acc[mt][nt][3]);
        }
    }
}

// ---------------------------------------------------------------------------
// GEMM2 (fp16 single-MMA): attn[c][d] = w16[c][q] . q16[q][d]  -> out right half
//        + fused ctx 128x128 tile copy into out LEFT half.
// CTA 128x128, 256 thr, warp 64x32, BK=16, THREE smem stages + DISTANCE-2
// register prefetch: ldg(kt+2) issued before body(kt), consumed by sts(kt+2)
// at the end of iter kt+1 -> ~2 iterations of LDG slack (covers DRAM latency;
// R14's distance-1 left the thin fp16 body stalled at tensor=31%).
// ---------------------------------------------------------------------------
#define BROWB2 272                 // B rows: 128 fp16 = 256B + 16B pad

__global__ __launch_bounds__(256, 2)
void ba_gemm2(const float* __restrict__ actx, float* __restrict__ gout)
{
    constexpr int NT = LQ / 16;                                    // 32
    constexpr int STAGE = 128 * AROWB + 16 * BROWB2;               // 10496
    constexpr int AOFF = 0, BOFF = 128 * AROWB;

    __shared__ __align__(16) char sm[3 * STAGE];                   // 31488
    const uint32_t sb = smem_u32(sm);

    const int tid  = threadIdx.x;
    const int lane = tid & 31;
    const int warp = tid >> 5;
    const int wm   = warp & 1;
    const int wn   = warp >> 1;        // 0..3, n offset 32*wn
    const int b  = blockIdx.z;
    const int yT = blockIdx.y;
    const int xT = blockIdx.x;

    const char* Aw = (const char*)g_w16 + ((size_t)b * LC + (size_t)yT * 128) * LQ * 2;
    const char* Bq = (const char*)g_q16 + ((size_t)b * LQ * DIM + (size_t)xT * 128) * 2;

    const int ar2 = tid >> 1, ac2 = (tid & 1) * 16;   // A: 128 rows x 32B
    const int kr2 = tid >> 4, nc2 = (tid & 15) * 16;  // B: 16 k-rows x 256B

    uint4 pa[2], pb[2];                                 // two prefetch sets
    auto ldg_tiles = [&](int kt, int s) {
        pa[s] = *(const uint4*)(Aw + (size_t)ar2 * (LQ * 2) + kt * 32 + ac2);
        pb[s] = *(const uint4*)(Bq + (size_t)(kt * 16 + kr2) * (DIM * 2) + nc2);
    };
    auto sts_stage = [&](int slot, int s) {
        const uint32_t s0 = slot * STAGE;
        *(uint4*)(sm + (s0 + AOFF + ar2 * AROWB + ac2))  = pa[s];
        *(uint4*)(sm + (s0 + BOFF + kr2 * BROWB2 + nc2)) = pb[s];
    };

    float acc[4][4][4];
#pragma unroll
    for (int m = 0; m < 4; m++)
#pragma unroll
        for (int n = 0; n < 4; n++)
#pragma unroll
            for (int j = 0; j < 4; j++) acc[m][n][j] = 0.f;

    // prologue: stage 0 in smem; set1 holds kt=1 data
    ldg_tiles(0, 0);
    sts_stage(0, 0);
    ldg_tiles(1, 1);
    __syncthreads();

    const int lrow = lane & 15;
    const int lkb  = lane & 16;

    for (int kt = 0; kt < NT; kt++) {
        // set (kt+1)&1 currently holds data(kt+1); set kt&1 is free
        if (kt + 2 < NT) ldg_tiles(kt + 2, kt & 1);

        const uint32_t s0 = (kt % 3) * STAGE;
        uint32_t af[4][4];
#pragma unroll
        for (int mt = 0; mt < 4; mt++) {
            uint32_t ra = sb + s0 + AOFF + (wm * 64 + mt * 16 + lrow) * AROWB + lkb;
            ldm4(ra, af[mt][0], af[mt][1], af[mt][2], af[mt][3]);
        }
#pragma unroll
        for (int p = 0; p < 2; p++) {
            uint32_t bh[4];
            uint32_t rb = sb + s0 + BOFF + lrow * BROWB2 + (wn * 32 + p * 16) * 2 + lkb;
            ldm4t(rb, bh[0], bh[1], bh[2], bh[3]);
#pragma unroll
            for (int mt = 0; mt < 4; mt++) {
                mma16816h(acc[mt][2 * p],     af[mt][0], af[mt][1], af[mt][2], af[mt][3], bh[0], bh[1]);
                mma16816h(acc[mt][2 * p + 1], af[mt][0], af[mt][1], af[mt][2], af[mt][3], bh[2], bh[3]);
            }
        }

        // publish stage kt+1 (written from the other register set)
        if (kt + 1 < NT) sts_stage((kt + 1) % 3, (kt + 1) & 1);
        __syncthreads();
    }

    // epilogue -> out right half
    const size_t rbase = (size_t)b * LC + (size_t)yT * 128 + wm * 64 + (lane >> 2);
    const int    cbase = DIM + xT * 128 + wn * 32 + (lane & 3) * 2;
#pragma unroll
    for (int mt = 0; mt < 4; mt++) {
#pragma unroll
        for (int nt = 0; nt < 4; nt++) {
            size_t r0 = (rbase + mt * 16) * (2 * DIM) + cbase + nt * 8;
            *(float2*)(gout + r0)                    = make_float2(acc[mt][nt][0], acc[mt][nt][1]);
            *(float2*)(gout + r0 + 8ull * (2 * DIM)) = make_float2(acc[mt][nt][2], acc[mt][nt][3]);
        }
    }

    // fused ctx copy into out LEFT half: this CTA's 128x128 tile
    {
        const float4* csrc = (const float4*)(actx + ((size_t)b * LC + (size_t)yT * 128) * DIM
                                             + (size_t)xT * 128);
        float4* cdst = (float4*)(gout + ((size_t)b * LC + (size_t)yT * 128) * (2 * DIM)
                                 + (size_t)xT * 128);
        const int crow = tid >> 5;      // 0..7
        const int ccol = tid & 31;      // 32 float4 = 128 floats
#pragma unroll
        for (int it = 0; it < 16; it++) {
            cdst[(size_t)(crow + it * 8) * (2 * DIM / 4) + ccol] =
                csrc[(size_t)(crow + it * 8) * (DIM / 4) + ccol];
        }
    }
}

// ---------------------------------------------------------------------------
// Warp-per-row softmax over 512 logits: fp32 in (g_attn), fp16 out (g_w16).
// ---------------------------------------------------------------------------
__global__ __launch_bounds__(256)
void ba_softmax(void)
{
    const int wid = threadIdx.x >> 5, lane = threadIdx.x & 31;
    const size_t row = (size_t)blockIdx.x * 8 + wid;
    const float4* p = (const float4*)(g_attn + row * LQ);

    float4 v[4];
    float mx = -1e30f;
#pragma unroll
    for (int i = 0; i < 4; i++) {
        v[i] = p[i * 32 + lane];
        mx = fmaxf(mx, fmaxf(fmaxf(v[i].x, v[i].y), fmaxf(v[i].z, v[i].w)));
    }
#pragma unroll
    for (int o = 16; o > 0; o >>= 1) mx = fmaxf(mx, __shfl_xor_sync(0xFFFFFFFFu, mx, o));

    float sum = 0.f;
#pragma unroll
    for (int i = 0; i < 4; i++) {
        v[i].x = __expf(v[i].x - mx); v[i].y = __expf(v[i].y - mx);
        v[i].z = __expf(v[i].z - mx); v[i].w = __expf(v[i].w - mx);
        sum += (v[i].x + v[i].y) + (v[i].z + v[i].w);
    }
#pragma unroll
    for (int o = 16; o > 0; o >>= 1) sum += __shfl_xor_sync(0xFFFFFFFFu, sum, o);

    const float inv = 1.0f / sum;
    uint2* pw = (uint2*)(g_w16 + row * LQ);
#pragma unroll
    for (int i = 0; i < 4; i++) {
        v[i].x *= inv; v[i].y *= inv; v[i].z *= inv; v[i].w *= inv;
        pw[i * 32 + lane] = pack4h(v[i]);
    }
}

// ---------------------------------------------------------------------------
extern "C" void kernel_launch(void* const* d_in, const int* in_sizes, int n_in,
                              void* d_out, int out_size)
{
    const float* question = (const float*)d_in[0];
    const float* context  = (const float*)d_in[1];
    if (in_sizes[0] > in_sizes[1]) {
        const float* t = question; question = context; context = t;
    }
    float* out = (float*)d_out;

    // pre-split Q (bf16 hi/lo for GEMM1, fp16 for GEMM2)
    ba_split_q<<<(size_t)BATCH * LQ * DIM / 4 / 256, 256>>>(question);

    // logits = ctx @ q^T -> g_attn (3-MMA bf16 split)
    ba_gemm1<<<dim3(LQ / 128, LC / 128, BATCH), 256>>>(context);
    // softmax -> fp16 weights
    ba_softmax<<<BATCH * LC / 8, 256>>>();
    // attn_out = w16 @ q16 (single fp16 MMA, distance-2 prefetch) -> right half
    ba_gemm2<<<dim3(DIM / 128, LC / 128, BATCH), 256>>>(context, out);
}

// round 17
// speedup vs baseline: 1.4506x; 1.2561x over previous
#include <cuda_runtime.h>
#include <cuda_bf16.h>
#include <cuda_fp16.h>
#include <cstdint>

#define BATCH 16
#define LQ    512
#define LC    2048
#define DIM   1024

// ---------------------------------------------------------------------------
// Device scratch (device-side only; symbols NEVER passed from host)
// ---------------------------------------------------------------------------
__device__ float  g_attn[(size_t)BATCH * LC * LQ];     // fp32 logits
__device__ __half g_q16 [(size_t)BATCH * LQ * DIM];    // fp16 q (both GEMMs)
__device__ __half g_w16 [(size_t)BATCH * LC * LQ];     // fp16 softmax weights

// ---------------------------------------------------------------------------
// helpers
// ---------------------------------------------------------------------------
__device__ __forceinline__ void ldm4(uint32_t a, uint32_t& r0, uint32_t& r1,
                                     uint32_t& r2, uint32_t& r3) {
    asm volatile("ldmatrix.sync.aligned.m8n8.x4.shared.b16 {%0,%1,%2,%3}, [%4];"
                 : "=r"(r0), "=r"(r1), "=r"(r2), "=r"(r3) : "r"(a));
}
__device__ __forceinline__ void ldm4t(uint32_t a, uint32_t& r0, uint32_t& r1,
                                      uint32_t& r2, uint32_t& r3) {
    asm volatile("ldmatrix.sync.aligned.m8n8.x4.trans.shared.b16 {%0,%1,%2,%3}, [%4];"
                 : "=r"(r0), "=r"(r1), "=r"(r2), "=r"(r3) : "r"(a));
}
__device__ __forceinline__ void mma16816h(float* c, uint32_t a0, uint32_t a1, uint32_t a2,
                                          uint32_t a3, uint32_t b0, uint32_t b1) {
    asm volatile(
        "mma.sync.aligned.m16n8k16.row.col.f32.f16.f16.f32 "
        "{%0,%1,%2,%3}, {%4,%5,%6,%7}, {%8,%9}, {%0,%1,%2,%3};"
        : "+f"(c[0]), "+f"(c[1]), "+f"(c[2]), "+f"(c[3])
        : "r"(a0), "r"(a1), "r"(a2), "r"(a3), "r"(b0), "r"(b1));
}
__device__ __forceinline__ uint32_t smem_u32(const void* p) {
    uint32_t a;
    asm("{ .reg .u64 t; cvta.to.shared.u64 t, %1; cvt.u32.u64 %0, t; }" : "=r"(a) : "l"(p));
    return a;
}
// split float4 into packed fp16 hi pair-words and fp16 lo (residual) pair-words
__device__ __forceinline__ void split4h(float4 v, uint32_t& h01, uint32_t& h23,
                                        uint32_t& l01, uint32_t& l23) {
    __half hx = __float2half_rn(v.x), hy = __float2half_rn(v.y);
    __half hz = __float2half_rn(v.z), hw = __float2half_rn(v.w);
    float lx = v.x - __half2float(hx), ly = v.y - __half2float(hy);
    float lz = v.z - __half2float(hz), lw = v.w - __half2float(hw);
    __half2 H0(hx, hy), H1(hz, hw);
    __half2 L0(__float2half_rn(lx), __float2half_rn(ly));
    __half2 L1(__float2half_rn(lz), __float2half_rn(lw));
    h01 = *(uint32_t*)&H0; h23 = *(uint32_t*)&H1;
    l01 = *(uint32_t*)&L0; l23 = *(uint32_t*)&L1;
}
// pack float4 -> two half2 words
__device__ __forceinline__ uint2 pack4h(float4 v) {
    __half2 a(__float2half_rn(v.x), __float2half_rn(v.y));
    __half2 b(__float2half_rn(v.z), __float2half_rn(v.w));
    return make_uint2(*(uint32_t*)&a, *(uint32_t*)&b);
}

// ---------------------------------------------------------------------------
// Q pre-convert: fp32 -> fp16 (used by BOTH GEMMs)
// ---------------------------------------------------------------------------
__global__ __launch_bounds__(256)
void ba_split_q(const float* __restrict__ src)
{
    const size_t i = (size_t)blockIdx.x * 256 + threadIdx.x;   // float4 index
    float4 v = ((const float4*)src)[i];
    ((uint2*)g_q16)[i] = pack4h(v);
}

// ---------------------------------------------------------------------------
// GEMM1: logits[c][q] = ctx[c][d] . q16[q][d] -> g_attn
// A = ctx split in-loop into fp16 hi/lo (A exact to ~2^-22); B = q single fp16.
// 2 MMAs per fragment pair (was 3 bf16 terms). Only error source: q's fp16
// rounding -> logit abs err ~6.4e-3 -> output contribution ~3.7e-4.
// CTA 128x128, 256 thr, warp 64x32, BK=16, double-buffered static smem.
// ---------------------------------------------------------------------------
#define AROWB 48                   // 16 halves = 32B + 16B pad (conflict-free)

__global__ __launch_bounds__(256, 2)
void ba_gemm1(const float* __restrict__ actx)
{
    constexpr int NT = DIM / 16;
    constexpr int STAGE = 3 * 128 * AROWB;                         // 18432
    constexpr int AH = 0, AL = 128 * AROWB, BF = 2 * 128 * AROWB;

    __shared__ __align__(16) char sm[2 * STAGE];                   // 36864
    const uint32_t sb = smem_u32(sm);

    const int tid  = threadIdx.x;
    const int lane = tid & 31;
    const int warp = tid >> 5;
    const int wm   = warp & 1;
    const int wn   = warp >> 1;        // 0..3, n offset 32*wn
    const int b  = blockIdx.z;
    const int yT = blockIdx.y;
    const int xT = blockIdx.x;

    const float* Abase_f = actx + ((size_t)b * LC + (size_t)yT * 128) * DIM;
    const char*  Bq = (const char*)g_q16 + ((size_t)b * LQ + (size_t)xT * 128) * DIM * 2;

    const int ar = tid >> 2, ac = tid & 3;          // A fp32: rows ar, ar+64
    const int br = tid >> 1, bc = (tid & 1) * 16;   // B fp16: row br, 16B chunk

    float4 pa0, pa1;
    uint4  pb;

    auto ldg_tiles = [&](int kt) {
        pa0 = *(const float4*)(Abase_f + (size_t)ar * DIM + kt * 16 + ac * 4);
        pa1 = *(const float4*)(Abase_f + (size_t)(ar + 64) * DIM + kt * 16 + ac * 4);
        pb  = *(const uint4*)(Bq + (size_t)br * (DIM * 2) + kt * 32 + bc);
    };
    auto sts_stage = [&](uint32_t s0) {
        uint32_t h0, h1, l0, l1;
        split4h(pa0, h0, h1, l0, l1);
        *(uint2*)(sm + (s0 + AH + ar * AROWB + ac * 8))        = make_uint2(h0, h1);
        *(uint2*)(sm + (s0 + AL + ar * AROWB + ac * 8))        = make_uint2(l0, l1);
        split4h(pa1, h0, h1, l0, l1);
        *(uint2*)(sm + (s0 + AH + (ar + 64) * AROWB + ac * 8)) = make_uint2(h0, h1);
        *(uint2*)(sm + (s0 + AL + (ar + 64) * AROWB + ac * 8)) = make_uint2(l0, l1);
        *(uint4*)(sm + (s0 + BF + br * AROWB + bc)) = pb;
    };

    float acc[4][4][4];
#pragma unroll
    for (int m = 0; m < 4; m++)
#pragma unroll
        for (int n = 0; n < 4; n++)
#pragma unroll
            for (int j = 0; j < 4; j++) acc[m][n][j] = 0.f;

    ldg_tiles(0);
    sts_stage(0);
    __syncthreads();

    const int lrow = lane & 15;
    const int lkb  = lane & 16;

    for (int kt = 0; kt < NT; kt++) {
        const uint32_t s0 = (kt & 1) * STAGE;
        if (kt + 1 < NT) ldg_tiles(kt + 1);

        uint32_t ahf[4][4], alf[4][4];
#pragma unroll
        for (int mt = 0; mt < 4; mt++) {
            uint32_t ra = sb + s0 + AH + (wm * 64 + mt * 16 + lrow) * AROWB + lkb;
            ldm4(ra, ahf[mt][0], ahf[mt][1], ahf[mt][2], ahf[mt][3]);
            uint32_t rl = sb + s0 + AL + (wm * 64 + mt * 16 + lrow) * AROWB + lkb;
            ldm4(rl, alf[mt][0], alf[mt][1], alf[mt][2], alf[mt][3]);
        }
#pragma unroll
        for (int p = 0; p < 2; p++) {
            uint32_t bh[4];
            uint32_t rb = sb + s0 + BF + (wn * 32 + p * 16 + lrow) * AROWB + lkb;
            ldm4(rb, bh[0], bh[1], bh[2], bh[3]);
#pragma unroll
            for (int mt = 0; mt < 4; mt++) {
                mma16816h(acc[mt][2 * p],     ahf[mt][0], ahf[mt][1], ahf[mt][2], ahf[mt][3], bh[0], bh[2]);
                mma16816h(acc[mt][2 * p + 1], ahf[mt][0], ahf[mt][1], ahf[mt][2], ahf[mt][3], bh[1], bh[3]);
                mma16816h(acc[mt][2 * p],     alf[mt][0], alf[mt][1], alf[mt][2], alf[mt][3], bh[0], bh[2]);
                mma16816h(acc[mt][2 * p + 1], alf[mt][0], alf[mt][1], alf[mt][2], alf[mt][3], bh[1], bh[3]);
            }
        }

        if (kt + 1 < NT) sts_stage(((kt + 1) & 1) * STAGE);
        __syncthreads();
    }

    float* Cg = (float*)g_attn;
    const size_t rbase = (size_t)b * LC + (size_t)yT * 128 + wm * 64 + (lane >> 2);
    const int    cbase = xT * 128 + wn * 32 + (lane & 3) * 2;
#pragma unroll
    for (int mt = 0; mt < 4; mt++) {
#pragma unroll
        for (int nt = 0; nt < 4; nt++) {
            size_t r0 = (rbase + mt * 16) * LQ + cbase + nt * 8;
            *(float2*)(Cg + r0)             = make_float2(acc[mt][nt][0], acc[mt][nt][1]);
            *(float2*)(Cg + r0 + 8ull * LQ) = make_float2(acc[mt][nt][2], acc[mt][nt][3]);
        }
    }
}

// ---------------------------------------------------------------------------
// GEMM2 (R16 verbatim, fp16 single-MMA): attn = w16 . q16 -> out right half
//        + fused ctx 128x128 tile copy into out LEFT half.
// CTA 128x128, 256 thr, warp 64x32, BK=16, 3 smem stages + distance-2
// register prefetch.
// ---------------------------------------------------------------------------
#define BROWB2 272                 // B rows: 128 fp16 = 256B + 16B pad

__global__ __launch_bounds__(256, 2)
void ba_gemm2(const float* __restrict__ actx, float* __restrict__ gout)
{
    constexpr int NT = LQ / 16;                                    // 32
    constexpr int STAGE = 128 * AROWB + 16 * BROWB2;               // 10496
    constexpr int AOFF = 0, BOFF = 128 * AROWB;

    __shared__ __align__(16) char sm[3 * STAGE];                   // 31488
    const uint32_t sb = smem_u32(sm);

    const int tid  = threadIdx.x;
    const int lane = tid & 31;
    const int warp = tid >> 5;
    const int wm   = warp & 1;
    const int wn   = warp >> 1;        // 0..3, n offset 32*wn
    const int b  = blockIdx.z;
    const int yT = blockIdx.y;
    const int xT = blockIdx.x;

    const char* Aw = (const char*)g_w16 + ((size_t)b * LC + (size_t)yT * 128) * LQ * 2;
    const char* Bq = (const char*)g_q16 + ((size_t)b * LQ * DIM + (size_t)xT * 128) * 2;

    const int ar2 = tid >> 1, ac2 = (tid & 1) * 16;   // A: 128 rows x 32B
    const int kr2 = tid >> 4, nc2 = (tid & 15) * 16;  // B: 16 k-rows x 256B

    uint4 pa[2], pb[2];                                 // two prefetch sets
    auto ldg_tiles = [&](int kt, int s) {
        pa[s] = *(const uint4*)(Aw + (size_t)ar2 * (LQ * 2) + kt * 32 + ac2);
        pb[s] = *(const uint4*)(Bq + (size_t)(kt * 16 + kr2) * (DIM * 2) + nc2);
    };
    auto sts_stage = [&](int slot, int s) {
        const uint32_t s0 = slot * STAGE;
        *(uint4*)(sm + (s0 + AOFF + ar2 * AROWB + ac2))  = pa[s];
        *(uint4*)(sm + (s0 + BOFF + kr2 * BROWB2 + nc2)) = pb[s];
    };

    float acc[4][4][4];
#pragma unroll
    for (int m = 0; m < 4; m++)
#pragma unroll
        for (int n = 0; n < 4; n++)
#pragma unroll
            for (int j = 0; j < 4; j++) acc[m][n][j] = 0.f;

    // prologue: stage 0 in smem; set1 holds kt=1 data
    ldg_tiles(0, 0);
    sts_stage(0, 0);
    ldg_tiles(1, 1);
    __syncthreads();

    const int lrow = lane & 15;
    const int lkb  = lane & 16;

    for (int kt = 0; kt < NT; kt++) {
        // set (kt+1)&1 currently holds data(kt+1); set kt&1 is free
        if (kt + 2 < NT) ldg_tiles(kt + 2, kt & 1);

        const uint32_t s0 = (kt % 3) * STAGE;
        uint32_t af[4][4];
#pragma unroll
        for (int mt = 0; mt < 4; mt++) {
            uint32_t ra = sb + s0 + AOFF + (wm * 64 + mt * 16 + lrow) * AROWB + lkb;
            ldm4(ra, af[mt][0], af[mt][1], af[mt][2], af[mt][3]);
        }
#pragma unroll
        for (int p = 0; p < 2; p++) {
            uint32_t bh[4];
            uint32_t rb = sb + s0 + BOFF + lrow * BROWB2 + (wn * 32 + p * 16) * 2 + lkb;
            ldm4t(rb, bh[0], bh[1], bh[2], bh[3]);
#pragma unroll
            for (int mt = 0; mt < 4; mt++) {
                mma16816h(acc[mt][2 * p],     af[mt][0], af[mt][1], af[mt][2], af[mt][3], bh[0], bh[1]);
                mma16816h(acc[mt][2 * p + 1], af[mt][0], af[mt][1], af[mt][2], af[mt][3], bh[2], bh[3]);
            }
        }

        // publish stage kt+1 (written from the other register set)
        if (kt + 1 < NT) sts_stage((kt + 1) % 3, (kt + 1) & 1);
        __syncthreads();
    }

    // epilogue -> out right half
    const size_t rbase = (size_t)b * LC + (size_t)yT * 128 + wm * 64 + (lane >> 2);
    const int    cbase = DIM + xT * 128 + wn * 32 + (lane & 3) * 2;
#pragma unroll
    for (int mt = 0; mt < 4; mt++) {
#pragma unroll
        for (int nt = 0; nt < 4; nt++) {
            size_t r0 = (rbase + mt * 16) * (2 * DIM) + cbase + nt * 8;
            *(float2*)(gout + r0)                    = make_float2(acc[mt][nt][0], acc[mt][nt][1]);
            *(float2*)(gout + r0 + 8ull * (2 * DIM)) = make_float2(acc[mt][nt][2], acc[mt][nt][3]);
        }
    }

    // fused ctx copy into out LEFT half: this CTA's 128x128 tile
    {
        const float4* csrc = (const float4*)(actx + ((size_t)b * LC + (size_t)yT * 128) * DIM
                                             + (size_t)xT * 128);
        float4* cdst = (float4*)(gout + ((size_t)b * LC + (size_t)yT * 128) * (2 * DIM)
                                 + (size_t)xT * 128);
        const int crow = tid >> 5;      // 0..7
        const int ccol = tid & 31;      // 32 float4 = 128 floats
#pragma unroll
        for (int it = 0; it < 16; it++) {
            cdst[(size_t)(crow + it * 8) * (2 * DIM / 4) + ccol] =
                csrc[(size_t)(crow + it * 8) * (DIM / 4) + ccol];
        }
    }
}

// ---------------------------------------------------------------------------
// Warp-per-row softmax over 512 logits: fp32 in (g_attn), fp16 out (g_w16).
// ---------------------------------------------------------------------------
__global__ __launch_bounds__(256)
void ba_softmax(void)
{
    const int wid = threadIdx.x >> 5, lane = threadIdx.x & 31;
    const size_t row = (size_t)blockIdx.x * 8 + wid;
    const float4* p = (const float4*)(g_attn + row * LQ);

    float4 v[4];
    float mx = -1e30f;
#pragma unroll
    for (int i = 0; i < 4; i++) {
        v[i] = p[i * 32 + lane];
        mx = fmaxf(mx, fmaxf(fmaxf(v[i].x, v[i].y), fmaxf(v[i].z, v[i].w)));
    }
#pragma unroll
    for (int o = 16; o > 0; o >>= 1) mx = fmaxf(mx, __shfl_xor_sync(0xFFFFFFFFu, mx, o));

    float sum = 0.f;
#pragma unroll
    for (int i = 0; i < 4; i++) {
        v[i].x = __expf(v[i].x - mx); v[i].y = __expf(v[i].y - mx);
        v[i].z = __expf(v[i].z - mx); v[i].w = __expf(v[i].w - mx);
        sum += (v[i].x + v[i].y) + (v[i].z + v[i].w);
    }
#pragma unroll
    for (int o = 16; o > 0; o >>= 1) sum += __shfl_xor_sync(0xFFFFFFFFu, sum, o);

    const float inv = 1.0f / sum;
    uint2* pw = (uint2*)(g_w16 + row * LQ);
#pragma unroll
    for (int i = 0; i < 4; i++) {
        v[i].x *= inv; v[i].y *= inv; v[i].z *= inv; v[i].w *= inv;
        pw[i * 32 + lane] = pack4h(v[i]);
    }
}

// ---------------------------------------------------------------------------
extern "C" void kernel_launch(void* const* d_in, const int* in_sizes, int n_in,
                              void* d_out, int out_size)
{
    const float* question = (const float*)d_in[0];
    const float* context  = (const float*)d_in[1];
    if (in_sizes[0] > in_sizes[1]) {
        const float* t = question; question = context; context = t;
    }
    float* out = (float*)d_out;

    // q -> fp16 (shared by both GEMMs)
    ba_split_q<<<(size_t)BATCH * LQ * DIM / 4 / 256, 256>>>(question);

    // logits = ctx @ q16^T -> g_attn (2-MMA fp16 split of A; B single fp16)
    ba_gemm1<<<dim3(LQ / 128, LC / 128, BATCH), 256>>>(context);
    // softmax -> fp16 weights
    ba_softmax<<<BATCH * LC / 8, 256>>>();
    // attn_out = w16 @ q16 (single fp16 MMA, distance-2 prefetch) -> right half
    ba_gemm2<<<dim3(DIM / 128, LC / 128, BATCH), 256>>>(context, out);
}